// round 12
// baseline (speedup 1.0000x reference)
#include <cuda_runtime.h>
#include <cuda_bf16.h>
#include <math.h>
#include <cstdint>

#define NN 32768
#define NE 49152
#define NB 1024
#define DD 64

// ---------------- device scratch (no allocations allowed) ----------------
__device__ __nv_bfloat16 g_h1[(size_t)NE * 128];    // edge MLP hidden (bf16)
__device__ __nv_bfloat16 g_e2[4096 * 128];          // e2_W (bf16)
__device__ __nv_bfloat16 g_Wb[(size_t)NE * 4096];   // edge weights (bf16, 402 MB)
__device__ float g_out[NN * DD];                    // node features / GRU h
__device__ float g_agg[NN * DD];                    // message accumulator
__device__ float g_cnt[NN];                         // in-degree (float)
__device__ int   g_gcnt[NB];                        // nodes per graph
__device__ int   g_gptr[NB + 1];                    // CSR over sorted batch
// transposed small weights (fp32 — bf16 here cost 10x rel_err for ~14us)
__device__ float g_gWihT[64 * 192];                 // gru Wih^T  [i][gate]
__device__ float g_gWhhT[64 * 192];                 // gru Whh^T
__device__ float g_lWihT[128 * 256];                // lstm Wih^T [k][gate]
__device__ float g_lWhhT[64 * 256];                 // lstm Whh^T
__device__ float g_fc1T[128 * 128];                 // fc1^T      [k][gate]

__device__ __forceinline__ float sigmoidf_(float x) { return 1.f / (1.f + expf(-x)); }

__device__ __forceinline__ uint32_t smem_u32(const void* p) {
    uint32_t a;
    asm("{ .reg .u64 t; cvta.to.shared.u64 t, %1; cvt.u32.u64 %0, t; }" : "=r"(a) : "l"(p));
    return a;
}
__device__ __forceinline__ void ldsm_x4(uint32_t& r0, uint32_t& r1, uint32_t& r2, uint32_t& r3,
                                        uint32_t addr) {
    asm volatile("ldmatrix.sync.aligned.m8n8.x4.shared.b16 {%0, %1, %2, %3}, [%4];"
                 : "=r"(r0), "=r"(r1), "=r"(r2), "=r"(r3) : "r"(addr));
}
__device__ __forceinline__ void mma16816(float* d, const uint32_t* a, const uint32_t* b) {
    asm volatile(
        "mma.sync.aligned.m16n8k16.row.col.f32.bf16.bf16.f32 "
        "{%0, %1, %2, %3}, {%4, %5, %6, %7}, {%8, %9}, {%0, %1, %2, %3};"
        : "+f"(d[0]), "+f"(d[1]), "+f"(d[2]), "+f"(d[3])
        : "r"(a[0]), "r"(a[1]), "r"(a[2]), "r"(a[3]), "r"(b[0]), "r"(b[1]));
}

// copy a [128 x 128 bf16] tile into smem with 16B-chunk XOR swizzle (512 thr)
__device__ __forceinline__ void copy_sw512(char* dst, const __nv_bfloat16* __restrict__ src) {
    int tid = threadIdx.x;
#pragma unroll
    for (int it = 0; it < 4; it++) {
        int i = tid + it * 512;
        int row = i >> 4;
        int chunk = i & 15;
        uint4 v = *(const uint4*)(src + (size_t)row * 128 + chunk * 8);
        *(uint4*)(dst + row * 256 + ((chunk ^ (row & 7)) << 4)) = v;
    }
}
__device__ __forceinline__ void copy_sw512_async(uint32_t dst, const __nv_bfloat16* __restrict__ src) {
    int tid = threadIdx.x;
#pragma unroll
    for (int it = 0; it < 4; it++) {
        int i = tid + it * 512;
        int row = i >> 4;
        int chunk = i & 15;
        uint32_t d = dst + row * 256 + ((chunk ^ (row & 7)) << 4);
        asm volatile("cp.async.cg.shared.global [%0], [%1], 16;"
                     :: "r"(d), "l"(src + (size_t)row * 128 + chunk * 8));
    }
}
#define CP_COMMIT() asm volatile("cp.async.commit_group;" ::: "memory")
#define CP_WAIT0()  asm volatile("cp.async.wait_group 0;" ::: "memory")

// ============ W GEMM (HMMA, 1-pass bf16) + FUSED iteration-1 messages =====
// g_Wb = bf16(h1 @ e2^T + b); simultaneously msg1[e] = v[src[e]] @ W[e]
// accumulated per-stripe in smem, atomically flushed to g_agg at the end.
// smem: A 32K | B0 32K | B1 32K | v 32K | macc 32K | stage 34.8K = 194 KB.
#define STG_STRIDE 272
#define WG_SMEM (98304 + 32768 + 32768 + 34816)
__global__ __launch_bounds__(512) void k_wgemm_tc(const float* __restrict__ e2b,
                                                  const int* __restrict__ ei) {
    extern __shared__ char dyn[];
    char* pA = dyn;
    char* pB0 = dyn + 32768;
    char* pB1 = dyn + 65536;
    float* vs = (float*)(dyn + 98304);      // [128][64] gathered src features
    float* macc = (float*)(dyn + 131072);   // [128][64] msg accumulator
    char* pStage = dyn + 163840;            // 128 x 272 B

    int tid = threadIdx.x, wid = tid >> 5, lane = tid & 31;
    int m0 = blockIdx.x * 128;
    int wm = wid & 3;
    int wn = wid >> 2;

    uint32_t uA = smem_u32(pA);
    uint32_t uB[2] = {smem_u32(pB0), smem_u32(pB1)};

    copy_sw512_async(uB[0], g_e2);
    CP_COMMIT();
    copy_sw512(pA, g_h1 + (size_t)m0 * 128);
    // gather v = out[src[e]] (iteration-1 node features) + zero macc
    for (int i = tid; i < 8192; i += 512) {
        int row = i >> 6, c = i & 63;
        vs[i] = g_out[ei[m0 + row] * 64 + c];
        macc[i] = 0.f;
    }

    int lrow = lane & 7;
    int lsel = lane >> 3;
    int a_row_off = (lsel & 1) * 8 + lrow;
    int a_chunk_sel = lsel >> 1;
    int b_row_off = (lsel >> 1) * 8 + lrow;
    int b_chunk_sel = lsel & 1;
    int g = lane >> 2, t4 = lane & 3;

    for (int s = 0; s < 32; s++) {
        CP_WAIT0();
        __syncthreads();             // B[s] + (first iter: A, vs) visible; stage drained
        if (s + 1 < 32) {
            copy_sw512_async(uB[(s + 1) & 1], g_e2 + (size_t)(s + 1) * 128 * 128);
            CP_COMMIT();
        }
        uint32_t uBc = uB[s & 1];

        float acc[2][4][4];
#pragma unroll
        for (int i = 0; i < 2; i++)
#pragma unroll
            for (int j = 0; j < 4; j++)
#pragma unroll
                for (int q = 0; q < 4; q++) acc[i][j][q] = 0.f;

#pragma unroll
        for (int ks = 0; ks < 8; ks++) {
            int c0 = ks * 2;
            uint32_t afr[2][4];
#pragma unroll
            for (int mt = 0; mt < 2; mt++) {
                int row = wm * 32 + mt * 16 + a_row_off;
                int ch = c0 + a_chunk_sel;
                uint32_t addr = uA + row * 256 + (((ch ^ (row & 7)) & 15) << 4);
                ldsm_x4(afr[mt][0], afr[mt][1], afr[mt][2], afr[mt][3], addr);
            }
            uint32_t bfr[2][4];
#pragma unroll
            for (int bt = 0; bt < 2; bt++) {
                int row = wn * 32 + bt * 16 + b_row_off;
                int ch = c0 + b_chunk_sel;
                uint32_t addr = uBc + row * 256 + (((ch ^ (row & 7)) & 15) << 4);
                ldsm_x4(bfr[bt][0], bfr[bt][1], bfr[bt][2], bfr[bt][3], addr);
            }
#pragma unroll
            for (int mt = 0; mt < 2; mt++)
#pragma unroll
                for (int nt = 0; nt < 4; nt++)
                    mma16816(acc[mt][nt], afr[mt], bfr[nt >> 1] + (nt & 1) * 2);
        }

        // stage bf16 tile (W + bias) for this stripe
#pragma unroll
        for (int mt = 0; mt < 2; mt++) {
            int r0 = wm * 32 + mt * 16 + g;
#pragma unroll
            for (int nt = 0; nt < 4; nt++) {
                int col = wn * 32 + nt * 8 + t4 * 2;
                float b0 = e2b[s * 128 + col], b1 = e2b[s * 128 + col + 1];
                __nv_bfloat162 v0 = __floats2bfloat162_rn(acc[mt][nt][0] + b0, acc[mt][nt][1] + b1);
                __nv_bfloat162 v1 = __floats2bfloat162_rn(acc[mt][nt][2] + b0, acc[mt][nt][3] + b1);
                *(__nv_bfloat162*)(pStage + r0 * STG_STRIDE + col * 2) = v0;
                *(__nv_bfloat162*)(pStage + (r0 + 8) * STG_STRIDE + col * 2) = v1;
            }
        }
        __syncthreads();
        // copy-out + fused msg1 accumulation. Stripe s = i in {2s, 2s+1}:
        // cols 0..63 are (i=2s, o), cols 64..127 are (i=2s+1, o).
#pragma unroll
        for (int it = 0; it < 4; it++) {
            int i = tid + it * 512;
            int row = i >> 4, ch = i & 15;
            uint4 v = *(const uint4*)(pStage + row * STG_STRIDE + ch * 16);
            *(uint4*)((char*)(g_Wb + (size_t)(m0 + row) * 4096 + s * 128) + ch * 16) = v;
        }
        {
            float v0c = 0.f, v1c = 0.f;   // per-thread rows handled below
#pragma unroll
            for (int it = 0; it < 16; it++) {
                int i = tid + it * 512;   // 8192 (row,o) pairs
                int row = i >> 6, o = i & 63;
                float w0 = __bfloat162float(*(const __nv_bfloat16*)(pStage + row * STG_STRIDE + o * 2));
                float w1 = __bfloat162float(*(const __nv_bfloat16*)(pStage + row * STG_STRIDE + (64 + o) * 2));
                macc[i] += vs[row * 64 + 2 * s] * w0 + vs[row * 64 + 2 * s + 1] * w1;
            }
            (void)v0c; (void)v1c;
        }
    }
    __syncthreads();
    // flush msg1 to g_agg
    for (int i = tid; i < 8192; i += 512) {
        int row = i >> 6, o = i & 63;
        atomicAdd(&g_agg[ei[NE + m0 + row] * 64 + o], macc[i]);
    }
}

// ---------------- prep: lin0 + zero state ---------------------------------
__global__ void k_prep(const float* __restrict__ x, const float* __restrict__ W,
                       const float* __restrict__ b) {
    int idx = blockIdx.x * blockDim.x + threadIdx.x;
    if (idx < NN * DD) {
        int n = idx >> 6, o = idx & 63;
        const float* xr = x + n * 14;
        const float* wr = W + o * 14;
        float acc = b[o];
#pragma unroll
        for (int i = 0; i < 14; i++) acc += xr[i] * wr[i];
        g_out[idx] = fmaxf(acc, 0.f);
        g_agg[idx] = 0.f;
    }
    if (idx < NN) g_cnt[idx] = 0.f;
    if (idx < NB) g_gcnt[idx] = 0;
}

// ---- edge MLP layer 1 (bf16) + e2_W cast + small-weight transposes -------
#define EP_T1 (NE * 128)
#define EP_T2 (4096 * 128)
#define EP_T3 (12288 + 32768 + 16384 + 16384)
__global__ void k_edgeprep(const float* __restrict__ ea, const float* __restrict__ W,
                           const float* __restrict__ b, const float* __restrict__ e2W,
                           const float* __restrict__ gWih, const float* __restrict__ gWhh,
                           const float* __restrict__ lWih, const float* __restrict__ lWhh,
                           const float* __restrict__ fc1W) {
    int idx = blockIdx.x * blockDim.x + threadIdx.x;
    if (idx < EP_T1) {
        int e = idx >> 7, j = idx & 127;
        const float* er = ea + e * 4;
        const float* wr = W + j * 4;
        float acc = b[j];
#pragma unroll
        for (int i = 0; i < 4; i++) acc += er[i] * wr[i];
        g_h1[idx] = __float2bfloat16(fmaxf(acc, 0.f));
    } else if (idx < EP_T1 + EP_T2) {
        int k = idx - EP_T1;
        g_e2[k] = __float2bfloat16(e2W[k]);
    } else {
        int t = idx - EP_T1 - EP_T2;
        if (t < 12288) {
            int i = t / 192, gate = t % 192;
            g_gWihT[t] = gWih[gate * 64 + i];
            g_gWhhT[t] = gWhh[gate * 64 + i];
        } else if (t < 12288 + 32768) {
            int k = t - 12288;
            g_lWihT[k] = lWih[(k % 256) * 128 + k / 256];
        } else if (t < 12288 + 32768 + 16384) {
            int k = t - 12288 - 32768;
            g_lWhhT[k] = lWhh[(k % 256) * 64 + k / 256];
        } else if (t < EP_T3) {
            int k = t - 12288 - 32768 - 16384;
            g_fc1T[k] = fc1W[(k % 128) * 128 + k / 128];
        }
    }
}

// ---------------- counts (in-degree + graph sizes) ------------------------
__global__ void k_counts(const int* __restrict__ ei, const int* __restrict__ batch) {
    int i = blockIdx.x * blockDim.x + threadIdx.x;
    if (i < NE) atomicAdd(&g_cnt[ei[NE + i]], 1.f);
    if (i < NN) atomicAdd(&g_gcnt[batch[i]], 1);
}
__global__ void k_scan() {
    __shared__ int s[NB];
    int t = threadIdx.x;
    s[t] = g_gcnt[t];
    __syncthreads();
    for (int off = 1; off < NB; off <<= 1) {
        int v = (t >= off) ? s[t - off] : 0;
        __syncthreads();
        s[t] += v;
        __syncthreads();
    }
    g_gptr[t + 1] = s[t];
    if (t == 0) g_gptr[0] = 0;
}

// ---------------- messages (iterations 2,3): warp/edge, vectorized -------
__global__ __launch_bounds__(256) void k_msg(const int* __restrict__ ei) {
    __shared__ float s[8][64];
    int tid = threadIdx.x, w = tid >> 5, l = tid & 31;
    int e0 = blockIdx.x * 8;
#pragma unroll
    for (int i = tid; i < 512; i += 256) {
        int el = i >> 6, c = i & 63;
        s[el][c] = g_out[ei[e0 + el] * 64 + c];
    }
    __syncthreads();
    int e = e0 + w;
    int dst = ei[NE + e];
    int co = (l & 7) * 8;
    int rb = l >> 3;
    float acc[8];
#pragma unroll
    for (int k = 0; k < 8; k++) acc[k] = 0.f;
    const __nv_bfloat16* Wr = g_Wb + (size_t)e * 4096;
#pragma unroll
    for (int r = 0; r < 16; r++) {
        int row = rb + r * 4;
        uint4 v = *(const uint4*)(Wr + row * 64 + co);
        float si = s[w][row];
        float2 f0 = __bfloat1622float2(*(__nv_bfloat162*)&v.x);
        float2 f1 = __bfloat1622float2(*(__nv_bfloat162*)&v.y);
        float2 f2 = __bfloat1622float2(*(__nv_bfloat162*)&v.z);
        float2 f3 = __bfloat1622float2(*(__nv_bfloat162*)&v.w);
        acc[0] += si * f0.x; acc[1] += si * f0.y;
        acc[2] += si * f1.x; acc[3] += si * f1.y;
        acc[4] += si * f2.x; acc[5] += si * f2.y;
        acc[6] += si * f3.x; acc[7] += si * f3.y;
    }
#pragma unroll
    for (int k = 0; k < 8; k++) {
        acc[k] += __shfl_xor_sync(0xffffffff, acc[k], 8);
        acc[k] += __shfl_xor_sync(0xffffffff, acc[k], 16);
    }
    int sub = l >> 3;
    atomicAdd(&g_agg[dst * 64 + co + sub * 2], acc[sub * 2]);
    atomicAdd(&g_agg[dst * 64 + co + sub * 2 + 1], acc[sub * 2 + 1]);
}

// ====== fused node update: m = relu(agg/cnt + h@rootW + cb); GRU ==========
#define ND_SMEM ((4096 + 2 * 64 * 66 + 2 * 16 * 192) * 4)
__global__ __launch_bounds__(256) void k_nodeup(const float* __restrict__ rootW,
                                                const float* __restrict__ convb,
                                                const float* __restrict__ bih,
                                                const float* __restrict__ bhh) {
    extern __shared__ float sdyn[];
    float* sW = sdyn;                       // 4096
    float* sm_ = sdyn + 4096;               // 64 x 66
    float* sh_ = sm_ + 64 * 66;             // 64 x 66
    float* sgi = sh_ + 64 * 66;             // 16 x 192
    float* sgh = sgi + 16 * 192;            // 16 x 192
    int tid = threadIdx.x;
    int base = blockIdx.x * 64;

    for (int i = tid; i < 4096; i += 256) {
        sW[i] = rootW[i];
        int n = i >> 6, c = i & 63;
        sh_[n * 66 + c] = g_out[(base + n) * 64 + c];
    }
    __syncthreads();

    {
        int o = tid & 63, ln = tid >> 6;
        float cb = convb[o];
        for (int g4 = 0; g4 < 16; g4++) {
            int n = g4 * 4 + ln;
            const float* hr = sh_ + n * 66;
            float acc = 0.f;
#pragma unroll
            for (int i = 0; i < 64; i++) acc += hr[i] * sW[i * 64 + o];
            int node = base + n;
            float c = g_cnt[node];
            if (c < 1.f) c = 1.f;
            float v = g_agg[node * 64 + o] / c + acc + cb;
            g_agg[node * 64 + o] = 0.f;
            sm_[n * 66 + o] = fmaxf(v, 0.f);
        }
    }
    __syncthreads();

    int gg = (tid % 48) * 4;
    int ng = (tid / 48) * 4;
    for (int nb = 0; nb < 4; nb++) {
        int nbase = nb * 16;
        if (tid < 192) {
            float accI[4][4], accH[4][4];
#pragma unroll
            for (int n = 0; n < 4; n++)
#pragma unroll
                for (int q = 0; q < 4; q++) { accI[n][q] = 0.f; accH[n][q] = 0.f; }
#pragma unroll 4
            for (int i = 0; i < 64; i++) {
                float4 wI = *(const float4*)(g_gWihT + i * 192 + gg);
                float4 wH = *(const float4*)(g_gWhhT + i * 192 + gg);
#pragma unroll
                for (int n = 0; n < 4; n++) {
                    float mi = sm_[(nbase + ng + n) * 66 + i];
                    float hi = sh_[(nbase + ng + n) * 66 + i];
                    accI[n][0] += mi * wI.x; accI[n][1] += mi * wI.y;
                    accI[n][2] += mi * wI.z; accI[n][3] += mi * wI.w;
                    accH[n][0] += hi * wH.x; accH[n][1] += hi * wH.y;
                    accH[n][2] += hi * wH.z; accH[n][3] += hi * wH.w;
                }
            }
            float4 bi = *(const float4*)(bih + gg);
            float4 bh = *(const float4*)(bhh + gg);
#pragma unroll
            for (int n = 0; n < 4; n++) {
                float* pi = sgi + (ng + n) * 192 + gg;
                float* ph = sgh + (ng + n) * 192 + gg;
                pi[0] = accI[n][0] + bi.x; pi[1] = accI[n][1] + bi.y;
                pi[2] = accI[n][2] + bi.z; pi[3] = accI[n][3] + bi.w;
                ph[0] = accH[n][0] + bh.x; ph[1] = accH[n][1] + bh.y;
                ph[2] = accH[n][2] + bh.z; ph[3] = accH[n][3] + bh.w;
            }
        }
        __syncthreads();
        for (int i = tid; i < 1024; i += 256) {
            int n = i >> 6, c = i & 63;
            float r = sigmoidf_(sgi[n * 192 + c] + sgh[n * 192 + c]);
            float z = sigmoidf_(sgi[n * 192 + 64 + c] + sgh[n * 192 + 64 + c]);
            float nn2 = tanhf(sgi[n * 192 + 128 + c] + r * sgh[n * 192 + 128 + c]);
            float hnew = (1.f - z) * nn2 + z * sh_[(nbase + n) * 66 + c];
            g_out[(base + nbase + n) * 64 + c] = hnew;
        }
        __syncthreads();
    }
}

// ====== fused Set2Set (3 steps) + final head; block = 1 graph =============
__global__ __launch_bounds__(256) void k_s2s(const float* __restrict__ lbih,
                                             const float* __restrict__ lbhh,
                                             const float* __restrict__ fc1b,
                                             const float* __restrict__ fc2W,
                                             const float* __restrict__ fc2b,
                                             float* __restrict__ outp) {
    __shared__ float qstar[128], shl[64], scl[64], sg[256], sa[256];
    int g = blockIdx.x, j = threadIdx.x;
    int s = g_gptr[g], e2 = g_gptr[g + 1];
    int cnt = e2 - s;
    if (j < 128) qstar[j] = 0.f;
    if (j < 64) { shl[j] = 0.f; scl[j] = 0.f; }
    __syncthreads();

    for (int step = 0; step < 3; step++) {
        float acc = lbih[j] + lbhh[j];
#pragma unroll 8
        for (int k = 0; k < 128; k++) acc += qstar[k] * g_lWihT[k * 256 + j];
#pragma unroll 8
        for (int k = 0; k < 64; k++) acc += shl[k] * g_lWhhT[k * 256 + j];
        sg[j] = acc;
        __syncthreads();
        if (j < 64) {
            float i_ = sg[j], f_ = sg[64 + j], gg_ = sg[128 + j], o_ = sg[192 + j];
            float c = sigmoidf_(f_) * scl[j] + sigmoidf_(i_) * tanhf(gg_);
            float h = sigmoidf_(o_) * tanhf(c);
            scl[j] = c;
            shl[j] = h;
        }
        __syncthreads();
        float mymax = -3.0e38f;
        for (int n = j; n < cnt; n += 256) {
            const float* orow = g_out + (size_t)(s + n) * 64;
            float d = 0.f;
#pragma unroll
            for (int i = 0; i < 64; i++) d += orow[i] * shl[i];
            sa[n] = d;
            mymax = fmaxf(mymax, d);
        }
        sg[j] = mymax;
        __syncthreads();
        for (int st = 128; st > 0; st >>= 1) {
            if (j < st) sg[j] = fmaxf(sg[j], sg[j + st]);
            __syncthreads();
        }
        float mx = sg[0];
        __syncthreads();
        float mysum = 0.f;
        for (int n = j; n < cnt; n += 256) {
            float ex = expf(sa[n] - mx);
            sa[n] = ex;
            mysum += ex;
        }
        sg[j] = mysum;
        __syncthreads();
        for (int st = 128; st > 0; st >>= 1) {
            if (j < st) sg[j] += sg[j + st];
            __syncthreads();
        }
        float den = sg[0];
        __syncthreads();
        if (j < 64) {
            float r = 0.f;
            for (int n = 0; n < cnt; n++) r += sa[n] * g_out[(size_t)(s + n) * 64 + j];
            if (cnt > 0) r /= den;
            qstar[j] = shl[j];
            qstar[64 + j] = r;
        }
        __syncthreads();
    }

    float val = 0.f;
    if (j < 128) {
        float a = fc1b[j];
#pragma unroll 8
        for (int k = 0; k < 128; k++) a += qstar[k] * g_fc1T[k * 128 + j];
        val = fmaxf(a, 0.f) * fc2W[j];
    }
    sg[j] = val;
    __syncthreads();
    for (int st = 128; st > 0; st >>= 1) {
        if (j < st) sg[j] += sg[j + st];
        __syncthreads();
    }
    if (j == 0) outp[g] = sg[0] + fc2b[0];
}

// ---------------- host: launch sequence ----------------------------------
extern "C" void kernel_launch(void* const* d_in, const int* in_sizes, int n_in,
                              void* d_out, int out_size) {
    const float* x       = (const float*)d_in[0];
    const int*   ei      = (const int*)d_in[1];
    const float* ea      = (const float*)d_in[2];
    const int*   batch   = (const int*)d_in[3];
    const float* lin0_W  = (const float*)d_in[4];
    const float* lin0_b  = (const float*)d_in[5];
    const float* e1_W    = (const float*)d_in[6];
    const float* e1_b    = (const float*)d_in[7];
    const float* e2_W    = (const float*)d_in[8];
    const float* e2_b    = (const float*)d_in[9];
    const float* root_W  = (const float*)d_in[10];
    const float* conv_b  = (const float*)d_in[11];
    const float* gru_Wih = (const float*)d_in[12];
    const float* gru_Whh = (const float*)d_in[13];
    const float* gru_bih = (const float*)d_in[14];
    const float* gru_bhh = (const float*)d_in[15];
    const float* lstm_Wih = (const float*)d_in[16];
    const float* lstm_Whh = (const float*)d_in[17];
    const float* lstm_bih = (const float*)d_in[18];
    const float* lstm_bhh = (const float*)d_in[19];
    const float* fc1_W   = (const float*)d_in[20];
    const float* fc1_b   = (const float*)d_in[21];
    const float* fc2_W   = (const float*)d_in[22];
    const float* fc2_b   = (const float*)d_in[23];
    float* outp = (float*)d_out;

    static bool attr_set = false;
    if (!attr_set) {
        cudaFuncSetAttribute(k_wgemm_tc, cudaFuncAttributeMaxDynamicSharedMemorySize, WG_SMEM);
        cudaFuncSetAttribute(k_nodeup, cudaFuncAttributeMaxDynamicSharedMemorySize, ND_SMEM);
        attr_set = true;
    }

    // k_wgemm_tc in slot #4 — the launch position ncu's window captures.
    k_prep<<<(NN * DD) / 256, 256>>>(x, lin0_W, lin0_b);
    k_edgeprep<<<(EP_T1 + EP_T2 + EP_T3 + 255) / 256, 256>>>(
        ea, e1_W, e1_b, e2_W, gru_Wih, gru_Whh, lstm_Wih, lstm_Whh, fc1_W);
    k_counts<<<NE / 256, 256>>>(ei, batch);
    k_wgemm_tc<<<NE / 128, 512, WG_SMEM>>>(e2_b, ei);   // includes msg for it=0
    k_scan<<<1, NB>>>();

    k_nodeup<<<NN / 64, 256, ND_SMEM>>>(root_W, conv_b, gru_bih, gru_bhh);  // it 0
    for (int it = 1; it < 3; it++) {
        k_msg<<<NE / 8, 256>>>(ei);
        k_nodeup<<<NN / 64, 256, ND_SMEM>>>(root_W, conv_b, gru_bih, gru_bhh);
    }

    k_s2s<<<NB, 256>>>(lstm_bih, lstm_bhh, fc1_b, fc2_W, fc2_b, outp);
}

// round 13
// speedup vs baseline: 1.5207x; 1.5207x over previous
#include <cuda_runtime.h>
#include <cuda_bf16.h>
#include <math.h>
#include <cstdint>

#define NN 32768
#define NE 49152
#define NB 1024
#define DD 64

// ---------------- device scratch (no allocations allowed) ----------------
__device__ __nv_bfloat16 g_h1[(size_t)NE * 128];    // edge MLP hidden (bf16)
__device__ __nv_bfloat16 g_e2[4096 * 128];          // e2_W (bf16)
__device__ __nv_bfloat16 g_Wb[(size_t)NE * 4096];   // edge weights (bf16, 402 MB)
__device__ float g_out[NN * DD];                    // node features / GRU h
__device__ float g_agg[NN * DD];                    // message accumulator
__device__ float g_cnt[NN];                         // in-degree (float)
__device__ int   g_gcnt[NB];                        // nodes per graph
__device__ int   g_gptr[NB + 1];                    // CSR over sorted batch
// transposed small weights (fp32 — bf16 here costs 10x rel_err)
__device__ float g_gWihT[64 * 192];                 // gru Wih^T  [i][gate]
__device__ float g_gWhhT[64 * 192];                 // gru Whh^T
__device__ float g_lWihT[128 * 256];                // lstm Wih^T [k][gate]
__device__ float g_lWhhT[64 * 256];                 // lstm Whh^T
__device__ float g_fc1T[128 * 128];                 // fc1^T      [k][gate]

__device__ __forceinline__ float sigmoidf_(float x) { return 1.f / (1.f + expf(-x)); }

__device__ __forceinline__ uint32_t smem_u32(const void* p) {
    uint32_t a;
    asm("{ .reg .u64 t; cvta.to.shared.u64 t, %1; cvt.u32.u64 %0, t; }" : "=r"(a) : "l"(p));
    return a;
}
__device__ __forceinline__ void ldsm_x4(uint32_t& r0, uint32_t& r1, uint32_t& r2, uint32_t& r3,
                                        uint32_t addr) {
    asm volatile("ldmatrix.sync.aligned.m8n8.x4.shared.b16 {%0, %1, %2, %3}, [%4];"
                 : "=r"(r0), "=r"(r1), "=r"(r2), "=r"(r3) : "r"(addr));
}
__device__ __forceinline__ void mma16816(float* d, const uint32_t* a, const uint32_t* b) {
    asm volatile(
        "mma.sync.aligned.m16n8k16.row.col.f32.bf16.bf16.f32 "
        "{%0, %1, %2, %3}, {%4, %5, %6, %7}, {%8, %9}, {%0, %1, %2, %3};"
        : "+f"(d[0]), "+f"(d[1]), "+f"(d[2]), "+f"(d[3])
        : "r"(a[0]), "r"(a[1]), "r"(a[2]), "r"(a[3]), "r"(b[0]), "r"(b[1]));
}

// copy a [128 x 128 bf16] tile into smem with 16B-chunk XOR swizzle (512 thr)
__device__ __forceinline__ void copy_sw512(char* dst, const __nv_bfloat16* __restrict__ src) {
    int tid = threadIdx.x;
#pragma unroll
    for (int it = 0; it < 4; it++) {
        int i = tid + it * 512;
        int row = i >> 4;
        int chunk = i & 15;
        uint4 v = *(const uint4*)(src + (size_t)row * 128 + chunk * 8);
        *(uint4*)(dst + row * 256 + ((chunk ^ (row & 7)) << 4)) = v;
    }
}
__device__ __forceinline__ void copy_sw512_async(uint32_t dst, const __nv_bfloat16* __restrict__ src) {
    int tid = threadIdx.x;
#pragma unroll
    for (int it = 0; it < 4; it++) {
        int i = tid + it * 512;
        int row = i >> 4;
        int chunk = i & 15;
        uint32_t d = dst + row * 256 + ((chunk ^ (row & 7)) << 4);
        asm volatile("cp.async.cg.shared.global [%0], [%1], 16;"
                     :: "r"(d), "l"(src + (size_t)row * 128 + chunk * 8));
    }
}
#define CP_COMMIT() asm volatile("cp.async.commit_group;" ::: "memory")
#define CP_WAIT0()  asm volatile("cp.async.wait_group 0;" ::: "memory")

// ============ W GEMM (HMMA, 1-pass bf16): g_Wb = bf16(h1 @ e2^T + b) ======
// EXACT round-10 structure (219us, 80 regs): no A-hoist, no fused msg —
// both variants regressed (regs/smem slack is zero in the stripe loop).
#define STG_STRIDE 272
#define WG_SMEM (98304 + 128 * STG_STRIDE)
__global__ __launch_bounds__(512) void k_wgemm_tc(const float* __restrict__ e2b) {
    extern __shared__ char dyn[];
    char* pA = dyn;
    char* pB0 = dyn + 32768;
    char* pB1 = dyn + 65536;
    char* pStage = dyn + 98304;

    int tid = threadIdx.x, wid = tid >> 5, lane = tid & 31;
    int m0 = blockIdx.x * 128;
    int wm = wid & 3;
    int wn = wid >> 2;

    uint32_t uA = smem_u32(pA);
    uint32_t uB[2] = {smem_u32(pB0), smem_u32(pB1)};

    copy_sw512_async(uB[0], g_e2);
    CP_COMMIT();
    copy_sw512(pA, g_h1 + (size_t)m0 * 128);

    int lrow = lane & 7;
    int lsel = lane >> 3;
    int a_row_off = (lsel & 1) * 8 + lrow;
    int a_chunk_sel = lsel >> 1;
    int b_row_off = (lsel >> 1) * 8 + lrow;
    int b_chunk_sel = lsel & 1;
    int g = lane >> 2, t4 = lane & 3;

    for (int s = 0; s < 32; s++) {
        CP_WAIT0();
        __syncthreads();
        if (s + 1 < 32) {
            copy_sw512_async(uB[(s + 1) & 1], g_e2 + (size_t)(s + 1) * 128 * 128);
            CP_COMMIT();
        }
        uint32_t uBc = uB[s & 1];

        float acc[2][4][4];
#pragma unroll
        for (int i = 0; i < 2; i++)
#pragma unroll
            for (int j = 0; j < 4; j++)
#pragma unroll
                for (int q = 0; q < 4; q++) acc[i][j][q] = 0.f;

#pragma unroll
        for (int ks = 0; ks < 8; ks++) {
            int c0 = ks * 2;
            uint32_t afr[2][4];
#pragma unroll
            for (int mt = 0; mt < 2; mt++) {
                int row = wm * 32 + mt * 16 + a_row_off;
                int ch = c0 + a_chunk_sel;
                uint32_t addr = uA + row * 256 + (((ch ^ (row & 7)) & 15) << 4);
                ldsm_x4(afr[mt][0], afr[mt][1], afr[mt][2], afr[mt][3], addr);
            }
            uint32_t bfr[2][4];
#pragma unroll
            for (int bt = 0; bt < 2; bt++) {
                int row = wn * 32 + bt * 16 + b_row_off;
                int ch = c0 + b_chunk_sel;
                uint32_t addr = uBc + row * 256 + (((ch ^ (row & 7)) & 15) << 4);
                ldsm_x4(bfr[bt][0], bfr[bt][1], bfr[bt][2], bfr[bt][3], addr);
            }
#pragma unroll
            for (int mt = 0; mt < 2; mt++)
#pragma unroll
                for (int nt = 0; nt < 4; nt++)
                    mma16816(acc[mt][nt], afr[mt], bfr[nt >> 1] + (nt & 1) * 2);
        }

#pragma unroll
        for (int mt = 0; mt < 2; mt++) {
            int r0 = wm * 32 + mt * 16 + g;
#pragma unroll
            for (int nt = 0; nt < 4; nt++) {
                int col = wn * 32 + nt * 8 + t4 * 2;
                float b0 = e2b[s * 128 + col], b1 = e2b[s * 128 + col + 1];
                __nv_bfloat162 v0 = __floats2bfloat162_rn(acc[mt][nt][0] + b0, acc[mt][nt][1] + b1);
                __nv_bfloat162 v1 = __floats2bfloat162_rn(acc[mt][nt][2] + b0, acc[mt][nt][3] + b1);
                *(__nv_bfloat162*)(pStage + r0 * STG_STRIDE + col * 2) = v0;
                *(__nv_bfloat162*)(pStage + (r0 + 8) * STG_STRIDE + col * 2) = v1;
            }
        }
        __syncthreads();
#pragma unroll
        for (int it = 0; it < 4; it++) {
            int i = tid + it * 512;
            int row = i >> 4, ch = i & 15;
            uint4 v = *(const uint4*)(pStage + row * STG_STRIDE + ch * 16);
            *(uint4*)((char*)(g_Wb + (size_t)(m0 + row) * 4096 + s * 128) + ch * 16) = v;
        }
    }
}

// ---------------- prep: lin0 + zero state ---------------------------------
__global__ void k_prep(const float* __restrict__ x, const float* __restrict__ W,
                       const float* __restrict__ b) {
    int idx = blockIdx.x * blockDim.x + threadIdx.x;
    if (idx < NN * DD) {
        int n = idx >> 6, o = idx & 63;
        const float* xr = x + n * 14;
        const float* wr = W + o * 14;
        float acc = b[o];
#pragma unroll
        for (int i = 0; i < 14; i++) acc += xr[i] * wr[i];
        g_out[idx] = fmaxf(acc, 0.f);
        g_agg[idx] = 0.f;
    }
    if (idx < NN) g_cnt[idx] = 0.f;
    if (idx < NB) g_gcnt[idx] = 0;
}

// ---- edge MLP layer 1 (bf16) + e2_W cast + small-weight transposes -------
#define EP_T1 (NE * 128)
#define EP_T2 (4096 * 128)
#define EP_T3 (12288 + 32768 + 16384 + 16384)
__global__ void k_edgeprep(const float* __restrict__ ea, const float* __restrict__ W,
                           const float* __restrict__ b, const float* __restrict__ e2W,
                           const float* __restrict__ gWih, const float* __restrict__ gWhh,
                           const float* __restrict__ lWih, const float* __restrict__ lWhh,
                           const float* __restrict__ fc1W) {
    int idx = blockIdx.x * blockDim.x + threadIdx.x;
    if (idx < EP_T1) {
        int e = idx >> 7, j = idx & 127;
        const float* er = ea + e * 4;
        const float* wr = W + j * 4;
        float acc = b[j];
#pragma unroll
        for (int i = 0; i < 4; i++) acc += er[i] * wr[i];
        g_h1[idx] = __float2bfloat16(fmaxf(acc, 0.f));
    } else if (idx < EP_T1 + EP_T2) {
        int k = idx - EP_T1;
        g_e2[k] = __float2bfloat16(e2W[k]);
    } else {
        int t = idx - EP_T1 - EP_T2;
        if (t < 12288) {
            int i = t / 192, gate = t % 192;
            g_gWihT[t] = gWih[gate * 64 + i];
            g_gWhhT[t] = gWhh[gate * 64 + i];
        } else if (t < 12288 + 32768) {
            int k = t - 12288;
            g_lWihT[k] = lWih[(k % 256) * 128 + k / 256];
        } else if (t < 12288 + 32768 + 16384) {
            int k = t - 12288 - 32768;
            g_lWhhT[k] = lWhh[(k % 256) * 64 + k / 256];
        } else if (t < EP_T3) {
            int k = t - 12288 - 32768 - 16384;
            g_fc1T[k] = fc1W[(k % 128) * 128 + k / 128];
        }
    }
}

// ---------------- counts (in-degree + graph sizes) ------------------------
__global__ void k_counts(const int* __restrict__ ei, const int* __restrict__ batch) {
    int i = blockIdx.x * blockDim.x + threadIdx.x;
    if (i < NE) atomicAdd(&g_cnt[ei[NE + i]], 1.f);
    if (i < NN) atomicAdd(&g_gcnt[batch[i]], 1);
}
__global__ void k_scan() {
    __shared__ int s[NB];
    int t = threadIdx.x;
    s[t] = g_gcnt[t];
    __syncthreads();
    for (int off = 1; off < NB; off <<= 1) {
        int v = (t >= off) ? s[t - off] : 0;
        __syncthreads();
        s[t] += v;
        __syncthreads();
    }
    g_gptr[t + 1] = s[t];
    if (t == 0) g_gptr[0] = 0;
}

// ---------------- messages: warp/edge, vectorized bf16 loads -------------
__global__ __launch_bounds__(256) void k_msg(const int* __restrict__ ei) {
    __shared__ float s[8][64];
    int tid = threadIdx.x, w = tid >> 5, l = tid & 31;
    int e0 = blockIdx.x * 8;
#pragma unroll
    for (int i = tid; i < 512; i += 256) {
        int el = i >> 6, c = i & 63;
        s[el][c] = g_out[ei[e0 + el] * 64 + c];
    }
    __syncthreads();
    int e = e0 + w;
    int dst = ei[NE + e];
    int co = (l & 7) * 8;
    int rb = l >> 3;
    float acc[8];
#pragma unroll
    for (int k = 0; k < 8; k++) acc[k] = 0.f;
    const __nv_bfloat16* Wr = g_Wb + (size_t)e * 4096;
#pragma unroll
    for (int r = 0; r < 16; r++) {
        int row = rb + r * 4;
        uint4 v = *(const uint4*)(Wr + row * 64 + co);
        float si = s[w][row];
        float2 f0 = __bfloat1622float2(*(__nv_bfloat162*)&v.x);
        float2 f1 = __bfloat1622float2(*(__nv_bfloat162*)&v.y);
        float2 f2 = __bfloat1622float2(*(__nv_bfloat162*)&v.z);
        float2 f3 = __bfloat1622float2(*(__nv_bfloat162*)&v.w);
        acc[0] += si * f0.x; acc[1] += si * f0.y;
        acc[2] += si * f1.x; acc[3] += si * f1.y;
        acc[4] += si * f2.x; acc[5] += si * f2.y;
        acc[6] += si * f3.x; acc[7] += si * f3.y;
    }
#pragma unroll
    for (int k = 0; k < 8; k++) {
        acc[k] += __shfl_xor_sync(0xffffffff, acc[k], 8);
        acc[k] += __shfl_xor_sync(0xffffffff, acc[k], 16);
    }
    int sub = l >> 3;
    atomicAdd(&g_agg[dst * 64 + co + sub * 2], acc[sub * 2]);
    atomicAdd(&g_agg[dst * 64 + co + sub * 2 + 1], acc[sub * 2 + 1]);
}

// ====== fused node update: m = relu(agg/cnt + h@rootW + cb); GRU ==========
#define ND_SMEM ((4096 + 2 * 64 * 66 + 2 * 16 * 192) * 4)
__global__ __launch_bounds__(256) void k_nodeup(const float* __restrict__ rootW,
                                                const float* __restrict__ convb,
                                                const float* __restrict__ bih,
                                                const float* __restrict__ bhh) {
    extern __shared__ float sdyn[];
    float* sW = sdyn;                       // 4096
    float* sm_ = sdyn + 4096;               // 64 x 66
    float* sh_ = sm_ + 64 * 66;             // 64 x 66
    float* sgi = sh_ + 64 * 66;             // 16 x 192
    float* sgh = sgi + 16 * 192;            // 16 x 192
    int tid = threadIdx.x;
    int base = blockIdx.x * 64;

    for (int i = tid; i < 4096; i += 256) {
        sW[i] = rootW[i];
        int n = i >> 6, c = i & 63;
        sh_[n * 66 + c] = g_out[(base + n) * 64 + c];
    }
    __syncthreads();

    {
        int o = tid & 63, ln = tid >> 6;
        float cb = convb[o];
        for (int g4 = 0; g4 < 16; g4++) {
            int n = g4 * 4 + ln;
            const float* hr = sh_ + n * 66;
            float acc = 0.f;
#pragma unroll
            for (int i = 0; i < 64; i++) acc += hr[i] * sW[i * 64 + o];
            int node = base + n;
            float c = g_cnt[node];
            if (c < 1.f) c = 1.f;
            float v = g_agg[node * 64 + o] / c + acc + cb;
            g_agg[node * 64 + o] = 0.f;
            sm_[n * 66 + o] = fmaxf(v, 0.f);
        }
    }
    __syncthreads();

    int gg = (tid % 48) * 4;
    int ng = (tid / 48) * 4;
    for (int nb = 0; nb < 4; nb++) {
        int nbase = nb * 16;
        if (tid < 192) {
            float accI[4][4], accH[4][4];
#pragma unroll
            for (int n = 0; n < 4; n++)
#pragma unroll
                for (int q = 0; q < 4; q++) { accI[n][q] = 0.f; accH[n][q] = 0.f; }
#pragma unroll 4
            for (int i = 0; i < 64; i++) {
                float4 wI = *(const float4*)(g_gWihT + i * 192 + gg);
                float4 wH = *(const float4*)(g_gWhhT + i * 192 + gg);
#pragma unroll
                for (int n = 0; n < 4; n++) {
                    float mi = sm_[(nbase + ng + n) * 66 + i];
                    float hi = sh_[(nbase + ng + n) * 66 + i];
                    accI[n][0] += mi * wI.x; accI[n][1] += mi * wI.y;
                    accI[n][2] += mi * wI.z; accI[n][3] += mi * wI.w;
                    accH[n][0] += hi * wH.x; accH[n][1] += hi * wH.y;
                    accH[n][2] += hi * wH.z; accH[n][3] += hi * wH.w;
                }
            }
            float4 bi = *(const float4*)(bih + gg);
            float4 bh = *(const float4*)(bhh + gg);
#pragma unroll
            for (int n = 0; n < 4; n++) {
                float* pi = sgi + (ng + n) * 192 + gg;
                float* ph = sgh + (ng + n) * 192 + gg;
                pi[0] = accI[n][0] + bi.x; pi[1] = accI[n][1] + bi.y;
                pi[2] = accI[n][2] + bi.z; pi[3] = accI[n][3] + bi.w;
                ph[0] = accH[n][0] + bh.x; ph[1] = accH[n][1] + bh.y;
                ph[2] = accH[n][2] + bh.z; ph[3] = accH[n][3] + bh.w;
            }
        }
        __syncthreads();
        for (int i = tid; i < 1024; i += 256) {
            int n = i >> 6, c = i & 63;
            float r = sigmoidf_(sgi[n * 192 + c] + sgh[n * 192 + c]);
            float z = sigmoidf_(sgi[n * 192 + 64 + c] + sgh[n * 192 + 64 + c]);
            float nn2 = tanhf(sgi[n * 192 + 128 + c] + r * sgh[n * 192 + 128 + c]);
            float hnew = (1.f - z) * nn2 + z * sh_[(nbase + n) * 66 + c];
            g_out[(base + nbase + n) * 64 + c] = hnew;
        }
        __syncthreads();
    }
}

// ====== fused Set2Set (3 steps) + final head; block = 4 graphs ============
// Gate GEMVs batched across 4 graphs: each weight scalar loaded once and
// applied 4x -> LSTM/fc1 weight L2 traffic 600 MB -> 150 MB.
__global__ __launch_bounds__(256) void k_s2s(const float* __restrict__ lbih,
                                             const float* __restrict__ lbhh,
                                             const float* __restrict__ fc1b,
                                             const float* __restrict__ fc2W,
                                             const float* __restrict__ fc2b,
                                             float* __restrict__ outp) {
    __shared__ float qs[4][128], shl[4][64], scl[4][64], sgt[4][256];
    __shared__ float sa[4][256], red[256];
    int g0 = blockIdx.x * 4, j = threadIdx.x;

    for (int i = j; i < 512; i += 256) ((float*)qs)[i] = 0.f;
    if (j < 256) { ((float*)shl)[j] = 0.f; ((float*)scl)[j] = 0.f; }
    __syncthreads();

    int sbeg[4], cnt[4];
#pragma unroll
    for (int g = 0; g < 4; g++) {
        sbeg[g] = g_gptr[g0 + g];
        cnt[g] = g_gptr[g0 + g + 1] - sbeg[g];
    }

    for (int step = 0; step < 3; step++) {
        // LSTM gates: thread j = gate j, batched over 4 graphs
        float acc[4];
        float bsum = lbih[j] + lbhh[j];
#pragma unroll
        for (int g = 0; g < 4; g++) acc[g] = bsum;
#pragma unroll 4
        for (int k = 0; k < 128; k++) {
            float w = g_lWihT[k * 256 + j];
#pragma unroll
            for (int g = 0; g < 4; g++) acc[g] += qs[g][k] * w;
        }
#pragma unroll 4
        for (int k = 0; k < 64; k++) {
            float w = g_lWhhT[k * 256 + j];
#pragma unroll
            for (int g = 0; g < 4; g++) acc[g] += shl[g][k] * w;
        }
#pragma unroll
        for (int g = 0; g < 4; g++) sgt[g][j] = acc[g];
        __syncthreads();
        // LSTM cell: j = g*64 + c
        {
            int g = j >> 6, c = j & 63;
            float i_ = sgt[g][c], f_ = sgt[g][64 + c];
            float gg_ = sgt[g][128 + c], o_ = sgt[g][192 + c];
            float cc = sigmoidf_(f_) * scl[g][c] + sigmoidf_(i_) * tanhf(gg_);
            float h = sigmoidf_(o_) * tanhf(cc);
            scl[g][c] = cc;
            shl[g][c] = h;
        }
        __syncthreads();

        // attention + softmax + readout per graph (sequential; small graphs)
        for (int g = 0; g < 4; g++) {
            int s = sbeg[g], c = cnt[g];
            float mymax = -3.0e38f;
            for (int n = j; n < c; n += 256) {
                const float* orow = g_out + (size_t)(s + n) * 64;
                float d = 0.f;
#pragma unroll
                for (int i = 0; i < 64; i++) d += orow[i] * shl[g][i];
                sa[g][n] = d;
                mymax = fmaxf(mymax, d);
            }
            red[j] = mymax;
            __syncthreads();
            for (int st = 128; st > 0; st >>= 1) {
                if (j < st) red[j] = fmaxf(red[j], red[j + st]);
                __syncthreads();
            }
            float mx = red[0];
            __syncthreads();
            float mysum = 0.f;
            for (int n = j; n < c; n += 256) {
                float ex = expf(sa[g][n] - mx);
                sa[g][n] = ex;
                mysum += ex;
            }
            red[j] = mysum;
            __syncthreads();
            for (int st = 128; st > 0; st >>= 1) {
                if (j < st) red[j] += red[j + st];
                __syncthreads();
            }
            float den = red[0];
            __syncthreads();
            if (j < 64) {
                float r = 0.f;
                for (int n = 0; n < c; n++) r += sa[g][n] * g_out[(size_t)(s + n) * 64 + j];
                if (c > 0) r /= den;
                qs[g][j] = shl[g][j];
                qs[g][64 + j] = r;
            }
            __syncthreads();
        }
    }

    // final head: j<128 computes fc1 gate j for all 4 graphs
    if (j < 128) {
        float a[4];
        float bb = fc1b[j];
#pragma unroll
        for (int g = 0; g < 4; g++) a[g] = bb;
#pragma unroll 4
        for (int k = 0; k < 128; k++) {
            float w = g_fc1T[k * 128 + j];
#pragma unroll
            for (int g = 0; g < 4; g++) a[g] += qs[g][k] * w;
        }
        float f2 = fc2W[j];
#pragma unroll
        for (int g = 0; g < 4; g++) sgt[g][j] = fmaxf(a[g], 0.f) * f2;
    }
    __syncthreads();
    // reduce 128 per graph: j = g*64 + c
    {
        int g = j >> 6, c = j & 63;
        red[j] = sgt[g][c] + sgt[g][64 + c];
    }
    __syncthreads();
    for (int st = 32; st > 0; st >>= 1) {
        if ((j & 63) < st) red[j] += red[j + st];
        __syncthreads();
    }
    if ((j & 63) == 0) outp[g0 + (j >> 6)] = red[j] + fc2b[0];
}

// ---------------- host: launch sequence ----------------------------------
extern "C" void kernel_launch(void* const* d_in, const int* in_sizes, int n_in,
                              void* d_out, int out_size) {
    const float* x       = (const float*)d_in[0];
    const int*   ei      = (const int*)d_in[1];
    const float* ea      = (const float*)d_in[2];
    const int*   batch   = (const int*)d_in[3];
    const float* lin0_W  = (const float*)d_in[4];
    const float* lin0_b  = (const float*)d_in[5];
    const float* e1_W    = (const float*)d_in[6];
    const float* e1_b    = (const float*)d_in[7];
    const float* e2_W    = (const float*)d_in[8];
    const float* e2_b    = (const float*)d_in[9];
    const float* root_W  = (const float*)d_in[10];
    const float* conv_b  = (const float*)d_in[11];
    const float* gru_Wih = (const float*)d_in[12];
    const float* gru_Whh = (const float*)d_in[13];
    const float* gru_bih = (const float*)d_in[14];
    const float* gru_bhh = (const float*)d_in[15];
    const float* lstm_Wih = (const float*)d_in[16];
    const float* lstm_Whh = (const float*)d_in[17];
    const float* lstm_bih = (const float*)d_in[18];
    const float* lstm_bhh = (const float*)d_in[19];
    const float* fc1_W   = (const float*)d_in[20];
    const float* fc1_b   = (const float*)d_in[21];
    const float* fc2_W   = (const float*)d_in[22];
    const float* fc2_b   = (const float*)d_in[23];
    float* outp = (float*)d_out;

    static bool attr_set = false;
    if (!attr_set) {
        cudaFuncSetAttribute(k_wgemm_tc, cudaFuncAttributeMaxDynamicSharedMemorySize, WG_SMEM);
        cudaFuncSetAttribute(k_nodeup, cudaFuncAttributeMaxDynamicSharedMemorySize, ND_SMEM);
        attr_set = true;
    }

    // k_wgemm_tc in slot #4 — the launch position ncu's window captures.
    k_prep<<<(NN * DD) / 256, 256>>>(x, lin0_W, lin0_b);
    k_edgeprep<<<(EP_T1 + EP_T2 + EP_T3 + 255) / 256, 256>>>(
        ea, e1_W, e1_b, e2_W, gru_Wih, gru_Whh, lstm_Wih, lstm_Whh, fc1_W);
    k_counts<<<NE / 256, 256>>>(ei, batch);
    k_wgemm_tc<<<NE / 128, 512, WG_SMEM>>>(e2_b);
    k_scan<<<1, NB>>>();

    for (int it = 0; it < 3; it++) {
        k_msg<<<NE / 8, 256>>>(ei);
        k_nodeup<<<NN / 64, 256, ND_SMEM>>>(root_W, conv_b, gru_bih, gru_bhh);
    }

    k_s2s<<<NB / 4, 256>>>(lstm_bih, lstm_bhh, fc1_b, fc2_W, fc2_b, outp);
}